// round 1
// baseline (speedup 1.0000x reference)
#include <cuda_runtime.h>

#define TB 16          // voxels per block
#define NT 128         // threads per block
#define WROW 208       // padded row stride (floats) of transposed weight tiles
#define TS 24          // time steps
#define HH 64          // hidden
#define G3 192         // 3*H gates

typedef unsigned long long u64;

static __device__ __forceinline__ u64 pk2(float lo, float hi) {
    u64 r; asm("mov.b64 %0, {%1, %2};" : "=l"(r) : "f"(lo), "f"(hi)); return r;
}
static __device__ __forceinline__ void upk2(u64 v, float &lo, float &hi) {
    asm("mov.b64 {%0, %1}, %2;" : "=f"(lo), "=f"(hi) : "l"(v));
}
// packed dual fp32 FMA (Blackwell f32x2 pipe, 2 FMAs per issue)
static __device__ __forceinline__ void fma2(u64 &d, u64 a, u64 b) {
    asm("fma.rn.f32x2 %0, %1, %2, %0;" : "+l"(d) : "l"(a), "l"(b));
}
static __device__ __forceinline__ float fsig(float x) {
    float e = __expf(-x);
    return __fdividef(1.f, 1.f + e);
}
static __device__ __forceinline__ float ftanh(float x) {
    x = fminf(fmaxf(x, -10.f), 10.f);
    float e = __expf(-2.f * x);
    return __fdividef(1.f - e, 1.f + e);
}

// one k-row of the gate matvec for 2 voxels x 12 gates (4r,4z,4n)
template<bool L0>
static __device__ __forceinline__ void gate_row(
    float hx0, float hx1, float xx0, float xx1,
    const float* whk, const float* wik,
    u64&R0a,u64&R0b,u64&Z0a,u64&Z0b,u64&X0a,u64&X0b,u64&H0a,u64&H0b,
    u64&R1a,u64&R1b,u64&Z1a,u64&Z1b,u64&X1a,u64&X1b,u64&H1a,u64&H1b)
{
    u64 h0p = pk2(hx0, hx0), h1p = pk2(hx1, hx1);
    ulonglong2 whR = *(const ulonglong2*)(whk);
    ulonglong2 whZ = *(const ulonglong2*)(whk + 64);
    ulonglong2 whN = *(const ulonglong2*)(whk + 128);
    fma2(R0a,h0p,whR.x); fma2(R0b,h0p,whR.y);
    fma2(Z0a,h0p,whZ.x); fma2(Z0b,h0p,whZ.y);
    fma2(H0a,h0p,whN.x); fma2(H0b,h0p,whN.y);
    fma2(R1a,h1p,whR.x); fma2(R1b,h1p,whR.y);
    fma2(Z1a,h1p,whZ.x); fma2(Z1b,h1p,whZ.y);
    fma2(H1a,h1p,whN.x); fma2(H1b,h1p,whN.y);
    if (!L0) {
        u64 x0p = pk2(xx0, xx0), x1p = pk2(xx1, xx1);
        ulonglong2 wiR = *(const ulonglong2*)(wik);
        ulonglong2 wiZ = *(const ulonglong2*)(wik + 64);
        ulonglong2 wiN = *(const ulonglong2*)(wik + 128);
        fma2(R0a,x0p,wiR.x); fma2(R0b,x0p,wiR.y);
        fma2(Z0a,x0p,wiZ.x); fma2(Z0b,x0p,wiZ.y);
        fma2(X0a,x0p,wiN.x); fma2(X0b,x0p,wiN.y);
        fma2(R1a,x1p,wiR.x); fma2(R1b,x1p,wiR.y);
        fma2(Z1a,x1p,wiZ.x); fma2(Z1b,x1p,wiZ.y);
        fma2(X1a,x1p,wiN.x); fma2(X1b,x1p,wiN.y);
    }
}

// one GRU layer over all T steps, activations updated in place in smem
template<bool L0>
static __device__ __forceinline__ void run_layer(
    float* __restrict__ act, float* __restrict__ hbuf,
    const float* __restrict__ wihT, const float* __restrict__ whhT,
    const float* __restrict__ bihs, const float* __restrict__ bhhs,
    const float* __restrict__ w0,  const float* __restrict__ vin,
    float* __restrict__ gsum, float* __restrict__ gn, int tid)
{
    const int l16 = tid & 15;
    const int vp  = tid >> 4;
    const int v0  = vp * 2, v1 = v0 + 1;
    const int g4  = l16 * 4;

    const float4 biR = *(const float4*)(bihs + g4);
    const float4 bhR = *(const float4*)(bhhs + g4);
    const float4 biZ = *(const float4*)(bihs + 64 + g4);
    const float4 bhZ = *(const float4*)(bhhs + 64 + g4);
    const float4 biN = *(const float4*)(bihs + 128 + g4);
    const float4 bhN = *(const float4*)(bhhs + 128 + g4);

    for (int t = 0; t < TS; ++t) {
        u64 R0a = pk2(biR.x + bhR.x, biR.y + bhR.y);
        u64 R0b = pk2(biR.z + bhR.z, biR.w + bhR.w);
        u64 Z0a = pk2(biZ.x + bhZ.x, biZ.y + bhZ.y);
        u64 Z0b = pk2(biZ.z + bhZ.z, biZ.w + bhZ.w);
        u64 X0a = pk2(biN.x, biN.y), X0b = pk2(biN.z, biN.w);
        u64 H0a = pk2(bhN.x, bhN.y), H0b = pk2(bhN.z, bhN.w);
        u64 R1a=R0a, R1b=R0b, Z1a=Z0a, Z1b=Z0b;
        u64 X1a=X0a, X1b=X0b, H1a=H0a, H1b=H0b;

        const float* a0 = act + (v0*TS + t)*HH;
        const float* a1 = act + (v1*TS + t)*HH;
        const float* h0 = hbuf + v0*HH;
        const float* h1 = hbuf + v1*HH;

        #pragma unroll 2
        for (int k = 0; k < HH; k += 2) {
            float2 hA = *(const float2*)(h0 + k);
            float2 hB = *(const float2*)(h1 + k);
            float2 xA = make_float2(0.f, 0.f), xB = make_float2(0.f, 0.f);
            if (!L0) { xA = *(const float2*)(a0 + k); xB = *(const float2*)(a1 + k); }
            const float* whk = whhT + k*WROW + g4;
            const float* wik = wihT + k*WROW + g4;
            gate_row<L0>(hA.x, hB.x, xA.x, xB.x, whk, wik,
                R0a,R0b,Z0a,Z0b,X0a,X0b,H0a,H0b,
                R1a,R1b,Z1a,Z1b,X1a,X1b,H1a,H1b);
            gate_row<L0>(hA.y, hB.y, xA.y, xB.y, whk + WROW, wik + WROW,
                R0a,R0b,Z0a,Z0b,X0a,X0b,H0a,H0b,
                R1a,R1b,Z1a,Z1b,X1a,X1b,H1a,H1b);
        }

        float r00,r01,r02,r03, z00,z01,z02,z03, x00,x01,x02,x03, q00,q01,q02,q03;
        float r10,r11,r12,r13, z10,z11,z12,z13, x10,x11,x12,x13, q10,q11,q12,q13;
        upk2(R0a,r00,r01); upk2(R0b,r02,r03);
        upk2(Z0a,z00,z01); upk2(Z0b,z02,z03);
        upk2(X0a,x00,x01); upk2(X0b,x02,x03);
        upk2(H0a,q00,q01); upk2(H0b,q02,q03);
        upk2(R1a,r10,r11); upk2(R1b,r12,r13);
        upk2(Z1a,z10,z11); upk2(Z1b,z12,z13);
        upk2(X1a,x10,x11); upk2(X1b,x12,x13);
        upk2(H1a,q10,q11); upk2(H1b,q12,q13);

        if (L0) {
            float xv0 = vin[v0*TS + t];
            float xv1 = vin[v1*TS + t];
            float4 wr = *(const float4*)(w0 + g4);
            float4 wz = *(const float4*)(w0 + 64 + g4);
            float4 wn = *(const float4*)(w0 + 128 + g4);
            r00 += xv0*wr.x; r01 += xv0*wr.y; r02 += xv0*wr.z; r03 += xv0*wr.w;
            z00 += xv0*wz.x; z01 += xv0*wz.y; z02 += xv0*wz.z; z03 += xv0*wz.w;
            x00 += xv0*wn.x; x01 += xv0*wn.y; x02 += xv0*wn.z; x03 += xv0*wn.w;
            r10 += xv1*wr.x; r11 += xv1*wr.y; r12 += xv1*wr.z; r13 += xv1*wr.w;
            z10 += xv1*wz.x; z11 += xv1*wz.y; z12 += xv1*wz.z; z13 += xv1*wz.w;
            x10 += xv1*wn.x; x11 += xv1*wn.y; x12 += xv1*wn.z; x13 += xv1*wn.w;
        }

        *(float4*)(gsum + v0*G3 + g4)        = make_float4(r00,r01,r02,r03);
        *(float4*)(gsum + v0*G3 + 64 + g4)   = make_float4(z00,z01,z02,z03);
        *(float4*)(gsum + v0*G3 + 128 + g4)  = make_float4(x00,x01,x02,x03);
        *(float4*)(gn   + v0*HH + g4)        = make_float4(q00,q01,q02,q03);
        *(float4*)(gsum + v1*G3 + g4)        = make_float4(r10,r11,r12,r13);
        *(float4*)(gsum + v1*G3 + 64 + g4)   = make_float4(z10,z11,z12,z13);
        *(float4*)(gsum + v1*G3 + 128 + g4)  = make_float4(x10,x11,x12,x13);
        *(float4*)(gn   + v1*HH + g4)        = make_float4(q10,q11,q12,q13);
        __syncthreads();

        // gate nonlinearity + state update (r,z,n GRU math)
        for (int idx = tid; idx < TB*HH; idx += NT) {
            int v = idx >> 6, j = idx & 63;
            float r  = fsig(gsum[v*G3 + j]);
            float z  = fsig(gsum[v*G3 + 64 + j]);
            float nn = ftanh(gsum[v*G3 + 128 + j] + r * gn[idx]);
            float hv = hbuf[idx];
            float hN = (1.f - z)*nn + z*hv;
            hbuf[idx] = hN;
            act[(v*TS + t)*HH + j] = hN;
        }
        __syncthreads();
    }
}

__global__ void __launch_bounds__(NT, 1)
fused_rnn_kernel(const float* __restrict__ x,   const int*   __restrict__ lengths,
                 const float* __restrict__ sf,  const float* __restrict__ bp,
                 const float* __restrict__ wih0,const float* __restrict__ whh0,
                 const float* __restrict__ bih0,const float* __restrict__ bhh0,
                 const float* __restrict__ wihL,const float* __restrict__ whhL,
                 const float* __restrict__ bihL,const float* __restrict__ bhhL,
                 const float* __restrict__ bng, const float* __restrict__ bnb,
                 const float* __restrict__ bnm, const float* __restrict__ bnv,
                 const float* __restrict__ fcW, const float* __restrict__ fcb,
                 const float* __restrict__ fcWo,const float* __restrict__ fcbo,
                 float* __restrict__ out)
{
    extern __shared__ float sm[];
    float* act  = sm;                       // 16*24*64 = 24576
    float* hbuf = act  + TB*TS*HH;          // 1024
    float* wihT = hbuf + TB*HH;             // 64*208 = 13312
    float* whhT = wihT + 64*WROW;           // 13312
    float* gsum = whhT + 64*WROW;           // 3072
    float* gn   = gsum + TB*G3;             // 1024
    float* vin  = gn   + TB*HH;             // 384
    float* bihs = vin  + TB*TS;             // 192
    float* bhhs = bihs + G3;                // 192
    float* w0   = bhhs + G3;                // 192   total 57280 floats = 229120 B

    const int tid = threadIdx.x;
    const int b0  = blockIdx.x * TB;
    const int n   = b0 >> 12;               // DHW = 4096 per batch item
    const int sb  = b0 & 4095;

    // load + scale input sequences (coalesced over spatial dim)
    const float s0 = sf[0], s1 = sf[1], s2 = sf[2];
    const float p0 = bp[0], p1 = bp[1], p2 = bp[2];
    for (int idx = tid; idx < TB*TS; idx += NT) {
        int t = idx >> 4, v = idx & 15;
        float xv = x[n*98304 + t*4096 + sb + v];
        int p = t % 3;
        float sc = (p == 0) ? s0 : ((p == 1) ? s1 : s2);
        float bb = (p == 0) ? p0 : ((p == 1) ? p1 : p2);
        vin[v*TS + t] = xv*sc + bb;
    }

    for (int l = 0; l < 4; ++l) {
        __syncthreads();
        if (l == 0) {
            for (int idx = tid; idx < 12288; idx += NT) {
                int g = idx >> 6, k = idx & 63;
                whhT[k*WROW + g] = whh0[idx];
            }
            for (int idx = tid; idx < G3; idx += NT) {
                w0[idx] = wih0[idx]; bihs[idx] = bih0[idx]; bhhs[idx] = bhh0[idx];
            }
        } else {
            const float* Wi = wihL + (l-1)*12288;
            const float* Wh = whhL + (l-1)*12288;
            for (int idx = tid; idx < 12288; idx += NT) {
                int g = idx >> 6, k = idx & 63;
                wihT[k*WROW + g] = Wi[idx];
                whhT[k*WROW + g] = Wh[idx];
            }
            for (int idx = tid; idx < G3; idx += NT) {
                bihs[idx] = bihL[(l-1)*G3 + idx];
                bhhs[idx] = bhhL[(l-1)*G3 + idx];
            }
        }
        for (int idx = tid; idx < TB*HH; idx += NT) hbuf[idx] = 0.f;
        __syncthreads();
        if (l == 0) run_layer<true >(act,hbuf,wihT,whhT,bihs,bhhs,w0,vin,gsum,gn,tid);
        else        run_layer<false>(act,hbuf,wihT,whhT,bihs,bhhs,w0,vin,gsum,gn,tid);
    }

    // select h[len-1] + h[len-4], then the MLP head (per-voxel, all in smem)
    const int len = lengths[n];
    const int t1 = len - 1, t2 = len - 4;
    float* A = gsum;   // reuse as ping-pong buffers (first 1024 floats)
    float* B = gn;
    for (int idx = tid; idx < TB*HH; idx += NT) {
        int v = idx >> 6, j = idx & 63;
        A[idx] = act[(v*TS + t1)*HH + j] + act[(v*TS + t2)*HH + j];
    }
    __syncthreads();
    for (int i = 0; i < 5; ++i) {
        for (int idx = tid; idx < TB*HH; idx += NT) {
            int j = idx & 63;
            float xx = A[idx];
            float y = bng[i*HH+j]*(xx - bnm[i*HH+j])*rsqrtf(bnv[i*HH+j] + 1e-5f) + bnb[i*HH+j];
            A[idx] = y * fsig(y);
        }
        __syncthreads();
        const float* Wl = fcW + i*4096;
        for (int idx = tid; idx < TB*HH; idx += NT) {
            int v = idx >> 6, o = idx & 63;
            float acc = fcb[i*HH + o];
            const float* wr = Wl + o*HH;
            const float* av = A + v*HH;
            #pragma unroll 8
            for (int j = 0; j < HH; ++j) acc += av[j]*wr[j];
            B[idx] = acc;
        }
        __syncthreads();
        float* tsw = A; A = B; B = tsw;
    }
    for (int idx = tid; idx < TB*HH; idx += NT) {
        int j = idx & 63;
        float xx = A[idx];
        float y = bng[5*HH+j]*(xx - bnm[5*HH+j])*rsqrtf(bnv[5*HH+j] + 1e-5f) + bnb[5*HH+j];
        A[idx] = y * fsig(y);
    }
    __syncthreads();
    if (tid < TB) {
        float acc = fcbo[0];
        const float* av = A + tid*HH;
        #pragma unroll 8
        for (int j = 0; j < HH; ++j) acc += av[j]*fcWo[j];
        out[b0 + tid] = acc;
    }
}

extern "C" void kernel_launch(void* const* d_in, const int* in_sizes, int n_in,
                              void* d_out, int out_size)
{
    const float* x     = (const float*)d_in[0];
    const int*   lens  = (const int*)  d_in[1];
    const float* sf    = (const float*)d_in[2];
    const float* bp    = (const float*)d_in[3];
    const float* wih0  = (const float*)d_in[4];
    const float* whh0  = (const float*)d_in[5];
    const float* bih0  = (const float*)d_in[6];
    const float* bhh0  = (const float*)d_in[7];
    const float* wihL  = (const float*)d_in[8];
    const float* whhL  = (const float*)d_in[9];
    const float* bihL  = (const float*)d_in[10];
    const float* bhhL  = (const float*)d_in[11];
    const float* bng   = (const float*)d_in[12];
    const float* bnb   = (const float*)d_in[13];
    const float* bnm   = (const float*)d_in[14];
    const float* bnv   = (const float*)d_in[15];
    const float* fcW   = (const float*)d_in[16];
    const float* fcb   = (const float*)d_in[17];
    const float* fcWo  = (const float*)d_in[18];
    const float* fcbo  = (const float*)d_in[19];
    float* out = (float*)d_out;

    const size_t smem = 57280 * sizeof(float);   // 229120 B
    cudaFuncSetAttribute(fused_rnn_kernel,
                         cudaFuncAttributeMaxDynamicSharedMemorySize, (int)smem);
    fused_rnn_kernel<<<1024, NT, smem>>>(
        x, lens, sf, bp, wih0, whh0, bih0, bhh0,
        wihL, whhL, bihL, bhhL, bng, bnb, bnm, bnv,
        fcW, fcb, fcWo, fcbo, out);
}

// round 3
// speedup vs baseline: 2.2251x; 2.2251x over previous
#include <cuda_runtime.h>

#define NT 512
#define TS 24
typedef unsigned long long u64;

// inter-layer activations: [t][j][v_global], 24*64*16384 floats = 100.7 MB
__device__ float g_act[TS * 64 * 16384];

// smem offsets (floats)
#define OFF_WH  0        // [g][k] 12288
#define OFF_WI  12288    // 12288
#define OFF_XS  24576    // 2 x 4096, [k][v] double buffer
#define OFF_HS  32768    // [j][v] 4096
#define OFF_SR  36864    // 4096
#define OFF_SZ  40960    // 4096
#define OFF_SXN 45056    // 4096
#define OFF_SHN 49152    // 4096
#define OFF_VIN 53248    // [t][v] 1536
#define OFF_BI  54784    // 192
#define OFF_BH  54976    // 192
#define OFF_W0  55168    // 192
#define SMEM_FLOATS 55360  // 221,440 B

static __device__ __forceinline__ u64 dup2(float v) {
    u64 r; asm("mov.b64 %0, {%1, %1};" : "=l"(r) : "f"(v)); return r;
}
static __device__ __forceinline__ void fma2(u64 &d, u64 a, u64 b) {
    asm("fma.rn.f32x2 %0, %1, %2, %0;" : "+l"(d) : "l"(a), "l"(b));
}
static __device__ __forceinline__ float fsig(float x) {
    float e = __expf(-x);
    return __fdividef(1.f, 1.f + e);
}
static __device__ __forceinline__ float ftanh(float x) {
    x = fminf(fmaxf(x, -10.f), 10.f);
    float e = __expf(-2.f * x);
    return __fdividef(1.f - e, 1.f + e);
}

// One GRU layer, all T steps. warp w: gates {4w..4w+3} of each r/z/n; lane: voxel pair.
template<bool L0>
static __device__ void layer_run(float* __restrict__ sm, int tid, int vbase)
{
    const int lane = tid & 31, w = tid >> 5;
    const int v0 = lane * 2, gR = w * 4;
    const float* wh  = sm + OFF_WH;
    const float* wi  = sm + OFF_WI;
    float*       hS  = sm + OFF_HS;
    const float* bi  = sm + OFF_BI;
    const float* bh  = sm + OFF_BH;
    const float* w0  = sm + OFF_W0;
    const float* vin = sm + OFF_VIN;

    for (int t = 0; t < TS; ++t) {
        const float* xc = sm + OFF_XS + (t & 1) * 4096;
        float*       xb = sm + OFF_XS + ((t + 1) & 1) * 4096;

        // register-prefetch next step's input tile from global scratch
        float4 pf0, pf1;
        if (!L0 && t + 1 < TS) {
            int q0 = tid, q1 = tid + NT;
            pf0 = *(const float4*)&g_act[(((t + 1) * 64 + (q0 >> 4)) << 14) + vbase + ((q0 & 15) << 2)];
            pf1 = *(const float4*)&g_act[(((t + 1) * 64 + (q1 >> 4)) << 14) + vbase + ((q1 & 15) << 2)];
        }

        u64 aR[4] = {0,0,0,0}, aZ[4] = {0,0,0,0};
        u64 aNX[4] = {0,0,0,0}, aNH[4] = {0,0,0,0};

        for (int k = 0; k < 64; k += 4) {
            float4 W[12];
            // pass 1: hidden-weight matvec
            #pragma unroll
            for (int i = 0; i < 4; ++i) {
                W[i]     = *(const float4*)(wh + (gR + i) * 64 + k);
                W[4 + i] = *(const float4*)(wh + (64 + gR + i) * 64 + k);
                W[8 + i] = *(const float4*)(wh + (128 + gR + i) * 64 + k);
            }
            #pragma unroll
            for (int kk = 0; kk < 4; ++kk) {
                u64 h2 = *(const u64*)(hS + (k + kk) * 64 + v0);
                #pragma unroll
                for (int i = 0; i < 4; ++i) {
                    float wr = kk==0?W[i].x   : kk==1?W[i].y   : kk==2?W[i].z   : W[i].w;
                    float wz = kk==0?W[4+i].x : kk==1?W[4+i].y : kk==2?W[4+i].z : W[4+i].w;
                    float wn = kk==0?W[8+i].x : kk==1?W[8+i].y : kk==2?W[8+i].z : W[8+i].w;
                    fma2(aR[i],  h2, dup2(wr));
                    fma2(aZ[i],  h2, dup2(wz));
                    fma2(aNH[i], h2, dup2(wn));
                }
            }
            // pass 2: input-weight matvec (layers > 0)
            if (!L0) {
                #pragma unroll
                for (int i = 0; i < 4; ++i) {
                    W[i]     = *(const float4*)(wi + (gR + i) * 64 + k);
                    W[4 + i] = *(const float4*)(wi + (64 + gR + i) * 64 + k);
                    W[8 + i] = *(const float4*)(wi + (128 + gR + i) * 64 + k);
                }
                #pragma unroll
                for (int kk = 0; kk < 4; ++kk) {
                    u64 x2 = *(const u64*)(xc + (k + kk) * 64 + v0);
                    #pragma unroll
                    for (int i = 0; i < 4; ++i) {
                        float wr = kk==0?W[i].x   : kk==1?W[i].y   : kk==2?W[i].z   : W[i].w;
                        float wz = kk==0?W[4+i].x : kk==1?W[4+i].y : kk==2?W[4+i].z : W[4+i].w;
                        float wn = kk==0?W[8+i].x : kk==1?W[8+i].y : kk==2?W[8+i].z : W[8+i].w;
                        fma2(aR[i],  x2, dup2(wr));
                        fma2(aZ[i],  x2, dup2(wz));
                        fma2(aNX[i], x2, dup2(wn));
                    }
                }
            }
        }

        // exchange gate sums via smem (256B-contiguous per-warp rows, conflict-free)
        #pragma unroll
        for (int i = 0; i < 4; ++i) {
            *(u64*)(sm + OFF_SR  + (gR + i) * 64 + v0) = aR[i];
            *(u64*)(sm + OFF_SZ  + (gR + i) * 64 + v0) = aZ[i];
            *(u64*)(sm + OFF_SHN + (gR + i) * 64 + v0) = aNH[i];
            if (!L0) *(u64*)(sm + OFF_SXN + (gR + i) * 64 + v0) = aNX[i];
        }
        if (!L0 && t + 1 < TS) {
            int q0 = tid, q1 = tid + NT;
            *(float4*)(xb + (q0 >> 4) * 64 + ((q0 & 15) << 2)) = pf0;
            *(float4*)(xb + (q1 >> 4) * 64 + ((q1 & 15) << 2)) = pf1;
        }
        __syncthreads();

        // combine: gate nonlinearities + state update + global act write
        #pragma unroll
        for (int it = 0; it < 8; ++it) {
            int idx = tid + it * NT, v = idx & 63, j = idx >> 6;
            float rs = sm[OFF_SR + j * 64 + v] + bi[j] + bh[j];
            float zs = sm[OFF_SZ + j * 64 + v] + bi[64 + j] + bh[64 + j];
            float hn = sm[OFF_SHN + j * 64 + v] + bh[128 + j];
            float xn;
            if (L0) {
                float xv = vin[t * 64 + v];
                rs += xv * w0[j];
                zs += xv * w0[64 + j];
                xn = xv * w0[128 + j] + bi[128 + j];
            } else {
                xn = sm[OFF_SXN + j * 64 + v] + bi[128 + j];
            }
            float r = fsig(rs), z = fsig(zs);
            float n = ftanh(xn + r * hn);
            float h = hS[j * 64 + v];
            h = (1.f - z) * n + z * h;
            hS[j * 64 + v] = h;
            g_act[((t * 64 + j) << 14) + vbase + v] = h;
        }
        __syncthreads();
    }
}

__global__ void __launch_bounds__(NT, 1)
fused_rnn_kernel(const float* __restrict__ x,   const int*   __restrict__ lengths,
                 const float* __restrict__ sf,  const float* __restrict__ bp,
                 const float* __restrict__ wih0,const float* __restrict__ whh0,
                 const float* __restrict__ bih0,const float* __restrict__ bhh0,
                 const float* __restrict__ wihL,const float* __restrict__ whhL,
                 const float* __restrict__ bihL,const float* __restrict__ bhhL,
                 const float* __restrict__ bng, const float* __restrict__ bnb,
                 const float* __restrict__ bnm, const float* __restrict__ bnv,
                 const float* __restrict__ fcW, const float* __restrict__ fcb,
                 const float* __restrict__ fcWo,const float* __restrict__ fcbo,
                 float* __restrict__ out)
{
    extern __shared__ float sm[];
    const int tid = threadIdx.x;
    const int vbase = blockIdx.x * 64;
    const int n  = vbase >> 12;
    const int sb = vbase & 4095;

    // scaled scalar input sequences vin[t][v]
    for (int idx = tid; idx < TS * 64; idx += NT) {
        int t = idx >> 6, v = idx & 63;
        int p = t % 3;
        sm[OFF_VIN + idx] = x[n * 98304 + t * 4096 + sb + v] * sf[p] + bp[p];
    }

    for (int l = 0; l < 4; ++l) {
        __syncthreads();
        if (l == 0) {
            for (int idx = tid; idx < 12288; idx += NT) sm[OFF_WH + idx] = whh0[idx];
            if (tid < 192) {
                sm[OFF_BI + tid] = bih0[tid];
                sm[OFF_BH + tid] = bhh0[tid];
                sm[OFF_W0 + tid] = wih0[tid];
            }
        } else {
            const float* Wi = wihL + (l - 1) * 12288;
            const float* Wh = whhL + (l - 1) * 12288;
            for (int idx = tid; idx < 12288; idx += NT) {
                sm[OFF_WH + idx] = Wh[idx];
                sm[OFF_WI + idx] = Wi[idx];
            }
            if (tid < 192) {
                sm[OFF_BI + tid] = bihL[(l - 1) * 192 + tid];
                sm[OFF_BH + tid] = bhhL[(l - 1) * 192 + tid];
            }
        }
        for (int idx = tid; idx < 4096; idx += NT) sm[OFF_HS + idx] = 0.f;
        if (l > 0) {  // first input tile (t=0) into x buffer 0
            #pragma unroll
            for (int jj = 0; jj < 2; ++jj) {
                int q = tid + jj * NT;
                int k = q >> 4, v4 = (q & 15) << 2;
                *(float4*)(sm + OFF_XS + k * 64 + v4) =
                    *(const float4*)&g_act[(k << 14) + vbase + v4];
            }
        }
        __syncthreads();
        if (l == 0) layer_run<true >(sm, tid, vbase);
        else        layer_run<false>(sm, tid, vbase);
    }

    // ---- head: sel = h[len-1] + h[len-4]; 5x (BN+SiLU+FC); BN+SiLU; out ----
    __syncthreads();
    for (int idx = tid; idx < 20480; idx += NT) sm[OFF_WH + idx] = fcW[idx];  // all 5 FC weights
    float* A = sm + OFF_XS;
    float* B = A + 4096;
    const int len = lengths[n];
    const int t1 = len - 1, t2 = len - 4;
    #pragma unroll
    for (int it = 0; it < 8; ++it) {
        int idx = tid + it * NT, v = idx & 63, j = idx >> 6;
        A[j * 64 + v] = g_act[((t1 * 64 + j) << 14) + vbase + v]
                      + g_act[((t2 * 64 + j) << 14) + vbase + v];
    }
    __syncthreads();
    for (int i = 0; i < 5; ++i) {
        #pragma unroll
        for (int it = 0; it < 8; ++it) {
            int idx = tid + it * NT, v = idx & 63, j = idx >> 6;
            float y = bng[i * 64 + j] * (A[j * 64 + v] - bnm[i * 64 + j])
                      * rsqrtf(bnv[i * 64 + j] + 1e-5f) + bnb[i * 64 + j];
            A[j * 64 + v] = y * fsig(y);
        }
        __syncthreads();
        const float* Wl = sm + OFF_WH + i * 4096;
        #pragma unroll
        for (int it = 0; it < 8; ++it) {
            int idx = tid + it * NT, v = idx & 63, o = idx >> 6;
            float acc = fcb[i * 64 + o];
            #pragma unroll 8
            for (int j = 0; j < 64; ++j) acc += A[j * 64 + v] * Wl[o * 64 + j];
            B[o * 64 + v] = acc;
        }
        __syncthreads();
        float* tswp = A; A = B; B = tswp;
    }
    #pragma unroll
    for (int it = 0; it < 8; ++it) {
        int idx = tid + it * NT, v = idx & 63, j = idx >> 6;
        float y = bng[5 * 64 + j] * (A[j * 64 + v] - bnm[5 * 64 + j])
                  * rsqrtf(bnv[5 * 64 + j] + 1e-5f) + bnb[5 * 64 + j];
        A[j * 64 + v] = y * fsig(y);
    }
    __syncthreads();
    if (tid < 64) {
        float acc = fcbo[0];
        #pragma unroll 8
        for (int j = 0; j < 64; ++j) acc += A[j * 64 + tid] * fcWo[j];
        out[vbase + tid] = acc;
    }
}

extern "C" void kernel_launch(void* const* d_in, const int* in_sizes, int n_in,
                              void* d_out, int out_size)
{
    const float* x     = (const float*)d_in[0];
    const int*   lens  = (const int*)  d_in[1];
    const float* sf    = (const float*)d_in[2];
    const float* bp    = (const float*)d_in[3];
    const float* wih0  = (const float*)d_in[4];
    const float* whh0  = (const float*)d_in[5];
    const float* bih0  = (const float*)d_in[6];
    const float* bhh0  = (const float*)d_in[7];
    const float* wihL  = (const float*)d_in[8];
    const float* whhL  = (const float*)d_in[9];
    const float* bihL  = (const float*)d_in[10];
    const float* bhhL  = (const float*)d_in[11];
    const float* bng   = (const float*)d_in[12];
    const float* bnb   = (const float*)d_in[13];
    const float* bnm   = (const float*)d_in[14];
    const float* bnv   = (const float*)d_in[15];
    const float* fcW   = (const float*)d_in[16];
    const float* fcb   = (const float*)d_in[17];
    const float* fcWo  = (const float*)d_in[18];
    const float* fcbo  = (const float*)d_in[19];
    float* out = (float*)d_out;

    const size_t smem = SMEM_FLOATS * sizeof(float);  // 221,440 B
    cudaFuncSetAttribute(fused_rnn_kernel,
                         cudaFuncAttributeMaxDynamicSharedMemorySize, (int)smem);
    fused_rnn_kernel<<<256, NT, smem>>>(
        x, lens, sf, bp, wih0, whh0, bih0, bhh0,
        wihL, whhL, bihL, bhhL, bng, bnb, bnm, bnv,
        fcW, fcb, fcWo, fcbo, out);
}